// round 3
// baseline (speedup 1.0000x reference)
#include <cuda_runtime.h>
#include <cuda_bf16.h>
#include <math.h>

// Problem constants
#define BB 8
#define LL 2048
#define DD 1330
#define H1C 32
// T = 2 (hardcoded throughout)

#define NEGINF (-1e30f)

// Scratch (device globals; no allocation allowed)
__device__ float g_p0[BB * LL * H1C];   // split-K partial 0
__device__ float g_p1[BB * LL * H1C];   // split-K partial 1
__device__ float g_em[BB * LL * 2];     // [B*L, 2]
__device__ float g_llh[BB];
__device__ unsigned g_done;

// ---------------------------------------------------------------------------
// Kernel A: partial = x @ w1 over a K-slice, 3xTF32 tensor-core GEMM.
// M=16384, N=32, K=1330 split into 2 slices of 672 (21 tiles of BK=32).
// Block: 256 threads (8 warps), BM=128. Warp w: rows 16w..16w+15, all 32 cols.
// A stored once in smem as fp32 (split in regs); B stored pre-split hi/lo.
// ---------------------------------------------------------------------------
#define MMA_TF32(c, a0, a1, a2, a3, b0, b1)                                   \
    asm volatile(                                                             \
        "mma.sync.aligned.m16n8k8.row.col.f32.tf32.tf32.f32 "                 \
        "{%0,%1,%2,%3}, {%4,%5,%6,%7}, {%8,%9}, {%0,%1,%2,%3};"               \
        : "+f"(c[0]), "+f"(c[1]), "+f"(c[2]), "+f"(c[3])                      \
        : "r"(a0), "r"(a1), "r"(a2), "r"(a3), "r"(b0), "r"(b1))

__device__ __forceinline__ unsigned cvt_tf32(float v) {
    unsigned r;
    asm("cvt.rna.tf32.f32 %0, %1;" : "=r"(r) : "f"(v));
    return r;
}

__global__ __launch_bounds__(256, 2) void gemm1_mma(
    const float* __restrict__ x, const float* __restrict__ w1)
{
    __shared__ float xs[128][36];        // raw fp32 A tile
    __shared__ float bhi[4][4][32][2];   // [kchunk][ngroup][lane][reg]
    __shared__ float blo[4][4][32][2];

    const int tid = threadIdx.x;
    const int warp = tid >> 5, lane = tid & 31;
    const int gr = lane >> 2, gc = lane & 3;
    const int row0 = blockIdx.x * 128;
    const int kbase = blockIdx.y * 672;
    const int NT = 21;

    const int jj = tid & 15;       // k-pair index (k = 2*jj, 2*jj+1)
    const int rld = tid >> 4;      // row base 0..15

    float acc[4][4];
#pragma unroll
    for (int n = 0; n < 4; n++)
#pragma unroll
        for (int r = 0; r < 4; r++) acc[n][r] = 0.f;

    float2 xv[8];
    float wv[4];

    // ---- prefetch tile 0 ----
    {
        int k0 = kbase;
        int kq = k0 + 2 * jj;
        bool ok = (kq < DD);
#pragma unroll
        for (int i = 0; i < 8; i++) {
            int r = row0 + rld + 16 * i;
            xv[i] = ok ? *(const float2*)(x + (size_t)r * DD + kq)
                       : make_float2(0.f, 0.f);
        }
#pragma unroll
        for (int i = 0; i < 4; i++) {
            int idx = i * 256 + tid;
            int kk = idx >> 5, c = idx & 31;
            int k = k0 + kk;
            wv[i] = (k < DD) ? w1[k * H1C + c] : 0.f;
        }
    }

    for (int t = 0; t < NT; t++) {
        __syncthreads();   // previous tile's compute done -> safe to overwrite
        // ---- STS phase ----
#pragma unroll
        for (int i = 0; i < 8; i++) {
            int r = rld + 16 * i;
            *(float2*)&xs[r][2 * jj] = xv[i];
        }
#pragma unroll
        for (int i = 0; i < 4; i++) {
            int idx = i * 256 + tid;
            int kk = idx >> 5, c = idx & 31;
            unsigned h = cvt_tf32(wv[i]);
            float lo = wv[i] - __uint_as_float(h);
            unsigned q = cvt_tf32(lo);
            int chunk = kk >> 3;
            int reg = (kk >> 2) & 1;
            int lanep = (c & 7) * 4 + (kk & 3);
            int ng = c >> 3;
            bhi[chunk][ng][lanep][reg] = __uint_as_float(h);
            blo[chunk][ng][lanep][reg] = __uint_as_float(q);
        }
        __syncthreads();

        // ---- prefetch next tile ----
        if (t + 1 < NT) {
            int k0 = kbase + (t + 1) * 32;
            int kq = k0 + 2 * jj;
            bool ok = (kq < DD);
#pragma unroll
            for (int i = 0; i < 8; i++) {
                int r = row0 + rld + 16 * i;
                xv[i] = ok ? *(const float2*)(x + (size_t)r * DD + kq)
                           : make_float2(0.f, 0.f);
            }
#pragma unroll
            for (int i = 0; i < 4; i++) {
                int idx = i * 256 + tid;
                int kk = idx >> 5, c = idx & 31;
                int k = k0 + kk;
                wv[i] = (k < DD) ? w1[k * H1C + c] : 0.f;
            }
        }

        // ---- compute tile ----
        const int wrow = warp * 16;
#pragma unroll
        for (int ch = 0; ch < 4; ch++) {
            int kc = ch * 8;
            // single LDS of raw A, split hi/lo in registers
            float a0 = xs[wrow + gr][kc + gc];
            float a1 = xs[wrow + 8 + gr][kc + gc];
            float a2 = xs[wrow + gr][kc + gc + 4];
            float a3 = xs[wrow + 8 + gr][kc + gc + 4];
            unsigned h0 = cvt_tf32(a0), h1 = cvt_tf32(a1);
            unsigned h2 = cvt_tf32(a2), h3 = cvt_tf32(a3);
            unsigned q0 = cvt_tf32(a0 - __uint_as_float(h0));
            unsigned q1 = cvt_tf32(a1 - __uint_as_float(h1));
            unsigned q2 = cvt_tf32(a2 - __uint_as_float(h2));
            unsigned q3 = cvt_tf32(a3 - __uint_as_float(h3));
#pragma unroll
            for (int ng = 0; ng < 4; ng++) {
                float2 bh = *(float2*)&bhi[ch][ng][lane][0];
                float2 bl = *(float2*)&blo[ch][ng][lane][0];
                unsigned bh0 = __float_as_uint(bh.x);
                unsigned bh1 = __float_as_uint(bh.y);
                unsigned bl0 = __float_as_uint(bl.x);
                unsigned bl1 = __float_as_uint(bl.y);
                MMA_TF32(acc[ng], h0, h1, h2, h3, bh0, bh1);
                MMA_TF32(acc[ng], h0, h1, h2, h3, bl0, bl1);
                MMA_TF32(acc[ng], q0, q1, q2, q3, bh0, bh1);
            }
        }
    }

    // ---- epilogue: write partial ----
    float* gp = blockIdx.y ? g_p1 : g_p0;
    const int rowa = row0 + warp * 16 + gr;
#pragma unroll
    for (int ng = 0; ng < 4; ng++) {
        int col = ng * 8 + 2 * gc;
        *(float2*)&gp[(size_t)rowa * H1C + col] =
            make_float2(acc[ng][0], acc[ng][1]);
        *(float2*)&gp[(size_t)(rowa + 8) * H1C + col] =
            make_float2(acc[ng][2], acc[ng][3]);
    }
}

// ---------------------------------------------------------------------------
// Kernel B: sum partials + bias, conv1d(k=3,pad=1,32->16)+relu, gemm2(16->2).
// 64 blocks x 256 threads; block covers 256 positions (aligned within batch).
// ---------------------------------------------------------------------------
__global__ __launch_bounds__(256) void conv_gemm2_kernel(
    const float* __restrict__ conv_w, const float* __restrict__ conv_b,
    const float* __restrict__ w2, const float* __restrict__ b2,
    const float* __restrict__ b1)
{
    __shared__ float hs[258][33];   // halo tile of h1
    __shared__ float wst[96][16];   // [k*32+c1][c2]
    __shared__ float cb[16];
    __shared__ float w2s[16][2];
    __shared__ float b2s[2];

    const int tid = threadIdx.x;
    if (blockIdx.x == 0 && tid == 0) g_done = 0;

    for (int i = tid; i < 96 * 16; i += 256) {
        int q = i >> 4, c2 = i & 15;
        int k = q >> 5, c1 = q & 31;
        wst[q][c2] = conv_w[c2 * 96 + c1 * 3 + k];   // conv_w [c2][c1][k]
    }
    if (tid < 16) cb[tid] = conv_b[tid];
    if (tid < 32) w2s[tid >> 1][tid & 1] = w2[tid];
    if (tid < 2) b2s[tid] = b2[tid];

    const int p0 = blockIdx.x * 256;
    const int lblk = p0 & (LL - 1);

    for (int idx = tid; idx < 258 * 32; idx += 256) {
        int row = idx >> 5, c = idx & 31;
        int l = lblk - 1 + row;
        float v = 0.f;
        if (l >= 0 && l < LL) {
            int g = p0 + row - 1;
            v = g_p0[(size_t)g * H1C + c] + g_p1[(size_t)g * H1C + c] + __ldg(&b1[c]);
        }
        hs[row][c] = v;
    }
    __syncthreads();

    float4 acc[4];
#pragma unroll
    for (int m = 0; m < 4; m++) acc[m] = make_float4(0, 0, 0, 0);
#pragma unroll
    for (int kk = 0; kk < 3; kk++) {
#pragma unroll
        for (int c1 = 0; c1 < 32; c1++) {
            float hv = hs[tid + kk][c1];
            int q = kk * 32 + c1;
#pragma unroll
            for (int m = 0; m < 4; m++) {
                float4 w = *(const float4*)&wst[q][m * 4];
                acc[m].x += hv * w.x; acc[m].y += hv * w.y;
                acc[m].z += hv * w.z; acc[m].w += hv * w.w;
            }
        }
    }
    float af[16];
#pragma unroll
    for (int m = 0; m < 4; m++) {
        af[m * 4 + 0] = acc[m].x; af[m * 4 + 1] = acc[m].y;
        af[m * 4 + 2] = acc[m].z; af[m * 4 + 3] = acc[m].w;
    }
    float e0 = b2s[0], e1 = b2s[1];
#pragma unroll
    for (int c2 = 0; c2 < 16; c2++) {
        float h = fmaxf(af[c2] + cb[c2], 0.f);
        e0 += h * w2s[c2][0];
        e1 += h * w2s[c2][1];
    }
    *(float2*)&g_em[(size_t)(p0 + tid) * 2] = make_float2(e0, e1);
}

// ---------------------------------------------------------------------------
// Kernel C: CRF via associative scans (+ merged final reduction).
// ---------------------------------------------------------------------------
__device__ __forceinline__ float lse2(float p, float q) {
    float mx = fmaxf(p, q), mn = fminf(p, q);
    return mx + log1pf(__expf(mn - mx));
}
__device__ __forceinline__ float4 lse_mm(float4 A, float4 B) {
    float4 C;
    C.x = lse2(A.x + B.x, A.y + B.z);
    C.y = lse2(A.x + B.y, A.y + B.w);
    C.z = lse2(A.z + B.x, A.w + B.z);
    C.w = lse2(A.z + B.y, A.w + B.w);
    return C;
}
__device__ __forceinline__ float4 max_mm(float4 A, float4 B) {
    float4 C;
    C.x = fmaxf(A.x + B.x, A.y + B.z);
    C.y = fmaxf(A.x + B.y, A.y + B.w);
    C.z = fmaxf(A.z + B.x, A.w + B.z);
    C.w = fmaxf(A.z + B.y, A.w + B.w);
    return C;
}
__device__ __forceinline__ unsigned comp2(unsigned a, unsigned b) {
    unsigned r0 = (a >> (b & 1)) & 1;
    unsigned r1 = (a >> ((b >> 1) & 1)) & 1;
    return r0 | (r1 << 1);
}

__global__ __launch_bounds__(256) void crf_kernel(
    const int* __restrict__ tlen, const int* __restrict__ labels,
    const float* __restrict__ start_trans, const float* __restrict__ end_trans,
    const float* __restrict__ trans, float* __restrict__ out)
{
    __shared__ float4 sf[256];
    __shared__ float4 sv[256];
    __shared__ unsigned char scomp[256];
    __shared__ float sred[256];

    const int b = blockIdx.x, tid = threadIdx.x;
    const int len = tlen[b];
    const float t00 = trans[0], t01 = trans[1], t10 = trans[2], t11 = trans[3];
    const float* emb = g_em + (size_t)b * LL * 2;

    float4 Pf = make_float4(0.f, NEGINF, NEGINF, 0.f);
    float4 Pv = Pf;
#pragma unroll
    for (int k = 1; k <= 8; k++) {
        int t = tid * 8 + k;
        if (t < len) {
            float m0 = emb[2 * t], m1 = emb[2 * t + 1];
            float4 M = make_float4(t00 + m0, t01 + m1, t10 + m0, t11 + m1);
            Pf = lse_mm(Pf, M);
            Pv = max_mm(Pv, M);
        }
    }
    sf[tid] = Pf; sv[tid] = Pv;
    __syncthreads();

    for (int off = 1; off < 256; off <<= 1) {
        float4 nf, nv;
        bool p = (tid >= off);
        if (p) { nf = lse_mm(sf[tid - off], sf[tid]); nv = max_mm(sv[tid - off], sv[tid]); }
        __syncthreads();
        if (p) { sf[tid] = nf; sv[tid] = nv; }
        __syncthreads();
    }

    const float a00 = start_trans[0] + emb[0];
    const float a01 = start_trans[1] + emb[1];
    const float e0 = end_trans[0], e1 = end_trans[1];

    float4 PF = sf[255];
    float f0 = lse2(a00 + PF.x, a01 + PF.z);
    float f1 = lse2(a00 + PF.y, a01 + PF.w);
    float norm = lse2(f0 + e0, f1 + e1);

    float4 PV = sv[255];
    float v0 = fmaxf(a00 + PV.x, a01 + PV.z);
    float v1 = fmaxf(a00 + PV.y, a01 + PV.w);
    int last = (v1 + e1 > v0 + e0) ? 1 : 0;

    float4 E = (tid == 0) ? make_float4(0.f, NEGINF, NEGINF, 0.f) : sv[tid - 1];
    float u0 = fmaxf(a00 + E.x, a01 + E.z);
    float u1 = fmaxf(a00 + E.y, a01 + E.w);
    unsigned g[8];
    unsigned cc = 2u;   // identity map
#pragma unroll
    for (int k = 1; k <= 8; k++) {
        int t = tid * 8 + k;
        unsigned gt;
        if (t < len) {
            float m0 = emb[2 * t], m1 = emb[2 * t + 1];
            float s00 = u0 + t00, s10 = u1 + t10;
            int i0 = (s10 > s00) ? 1 : 0;
            float n0 = fmaxf(s00, s10) + m0;
            float s01 = u0 + t01, s11 = u1 + t11;
            int i1 = (s11 > s01) ? 1 : 0;
            float n1 = fmaxf(s01, s11) + m1;
            gt = (unsigned)(i0 | (i1 << 1));
            u0 = n0; u1 = n1;
        } else {
            gt = 2u;   // identity
        }
        g[k - 1] = gt;
        cc = comp2(cc, gt);
    }
    scomp[tid] = (unsigned char)cc;
    __syncthreads();

    for (int off = 1; off < 256; off <<= 1) {
        unsigned nc = 0;
        bool p = (tid + off < 256);
        if (p) nc = comp2(scomp[tid], scomp[tid + off]);
        __syncthreads();
        if (p) scomp[tid] = (unsigned char)nc;
        __syncthreads();
    }
    unsigned suf_next = (tid == 255) ? 2u : (unsigned)scomp[tid + 1];
    unsigned xx = (suf_next >> last) & 1u;

    float* tout = out + 1 + (size_t)b * LL;
#pragma unroll
    for (int k = 8; k >= 1; k--) {
        xx = (g[k - 1] >> xx) & 1u;
        int pos = tid * 8 + k - 1;
        tout[pos] = (pos < len) ? (float)xx : 0.f;
    }

    const int* lab = labels + (size_t)b * LL;
    float sc = 0.f;
#pragma unroll
    for (int k = 1; k <= 8; k++) {
        int t = tid * 8 + k;
        if (t < len) {
            int lp = lab[t - 1], lc = lab[t];
            sc += trans[lp * 2 + lc] + emb[2 * t + lc];
        }
    }
    sred[tid] = sc;
    __syncthreads();
    for (int off = 128; off > 0; off >>= 1) {
        if (tid < off) sred[tid] += sred[tid + off];
        __syncthreads();
    }
    if (tid == 0) {
        int l0 = lab[0];
        float total = sred[0] + start_trans[l0] + emb[l0];
        int le = lab[len - 1];
        total += end_trans[le];
        g_llh[b] = total - norm;
        __threadfence();
        unsigned old = atomicAdd(&g_done, 1);
        if (old == BB - 1) {
            __threadfence();
            float s = 0.f;
#pragma unroll
            for (int i = 0; i < BB; i++) s += ((volatile float*)g_llh)[i];
            out[0] = -s;
        }
    }
}

extern "C" void kernel_launch(void* const* d_in, const int* in_sizes, int n_in,
                              void* d_out, int out_size)
{
    const float* x       = (const float*)d_in[0];
    const int*   tlen    = (const int*)d_in[1];
    const int*   labels  = (const int*)d_in[2];
    const float* w1      = (const float*)d_in[3];
    const float* b1      = (const float*)d_in[4];
    const float* conv_w  = (const float*)d_in[5];
    const float* conv_b  = (const float*)d_in[6];
    const float* w2      = (const float*)d_in[7];
    const float* b2      = (const float*)d_in[8];
    const float* st      = (const float*)d_in[9];
    const float* en      = (const float*)d_in[10];
    const float* tr      = (const float*)d_in[11];
    float* out = (float*)d_out;

    gemm1_mma<<<dim3(128, 2), 256>>>(x, w1);
    conv_gemm2_kernel<<<64, 256>>>(conv_w, conv_b, w2, b2, b1);
    crf_kernel<<<BB, 256>>>(tlen, labels, st, en, tr, out);
}

// round 4
// speedup vs baseline: 1.2635x; 1.2635x over previous
#include <cuda_runtime.h>
#include <cuda_bf16.h>
#include <cuda_fp16.h>
#include <math.h>

// Problem constants
#define BB 8
#define LL 2048
#define DD 1330
#define H1C 32
// T = 2 (hardcoded throughout)

#define NEGINF (-1e30f)
#define NTILE 42          // ceil(1330/32) padded: 2 slices * 21 tiles

// Scratch (device globals; no allocation allowed)
__device__ float g_p0[BB * LL * H1C];   // split-K partial 0
__device__ float g_p1[BB * LL * H1C];   // split-K partial 1
__device__ float g_em[BB * LL * 2];     // [B*L, 2]
__device__ float g_llh[BB];
__device__ unsigned g_done;
// B fragments, fragment-order: [tile][ch][ng][lane] -> {bh0,bh1,bm0,bm1}
__device__ uint4 g_bfrag[NTILE * 2 * 4 * 32];

// ---------------------------------------------------------------------------
// fp16 helpers
// ---------------------------------------------------------------------------
__device__ __forceinline__ void split_pair(float f0, float f1,
                                           unsigned& hi, unsigned& mid) {
    __half h0 = __float2half_rn(f0), h1 = __float2half_rn(f1);
    float r0 = f0 - __half2float(h0);
    float r1 = f1 - __half2float(h1);
    __half2 H = __halves2half2(h0, h1);                       // lo=f0, hi=f1
    __half2 M = __halves2half2(__float2half_rn(r0), __float2half_rn(r1));
    hi = *(unsigned*)&H;
    mid = *(unsigned*)&M;
}

#define MMA_F16(c, a0, a1, a2, a3, b0, b1)                                    \
    asm volatile(                                                             \
        "mma.sync.aligned.m16n8k16.row.col.f32.f16.f16.f32 "                  \
        "{%0,%1,%2,%3}, {%4,%5,%6,%7}, {%8,%9}, {%0,%1,%2,%3};"               \
        : "+f"(c[0]), "+f"(c[1]), "+f"(c[2]), "+f"(c[3])                      \
        : "r"(a0), "r"(a1), "r"(a2), "r"(a3), "r"(b0), "r"(b1))

// ---------------------------------------------------------------------------
// Kernel 0: precompute B fragments (hi/mid fp16 split of w1, fragment order).
// Logical k mapping within a 32-k tile: k = 8*gc + 4*ch + 2*h + b
//   (gc = lane&3, ch = k16-chunk, h = reg index, b = element-in-pair)
// ---------------------------------------------------------------------------
__global__ __launch_bounds__(256) void prep_b(const float* __restrict__ w1) {
    int idx = blockIdx.x * 256 + threadIdx.x;   // 0 .. 10751
    int lane = idx & 31;
    int ng = (idx >> 5) & 3;
    int ch = (idx >> 7) & 1;
    int t = idx >> 8;
    if (t >= NTILE) return;
    int gr = lane >> 2, gc = lane & 3;
    int c = ng * 8 + gr;
    int kb = t * 32 + 8 * gc + 4 * ch;
    float f[4];
#pragma unroll
    for (int b = 0; b < 4; b++) {
        int k = kb + b;
        f[b] = (k < DD) ? w1[k * H1C + c] : 0.f;
    }
    uint4 o;
    split_pair(f[0], f[1], o.x, o.z);   // b0 hi, b0 mid
    split_pair(f[2], f[3], o.y, o.w);   // b1 hi, b1 mid
    g_bfrag[idx] = o;
}

// ---------------------------------------------------------------------------
// Kernel A: partial = x @ w1 over a K-slice, 3xFP16-split tensor GEMM.
// M=16384, N=32, K split in 2 slices of 672 (21 tiles of 32).
// Block: 256 threads (8 warps), BM=128; warp w: rows 16w..16w+15, cols 0..31.
// ---------------------------------------------------------------------------
__global__ __launch_bounds__(256, 2) void gemm1_mma(
    const float* __restrict__ x)
{
    __shared__ float xs[128][36];        // raw fp32 A tile (k-major)

    const int tid = threadIdx.x;
    const int warp = tid >> 5, lane = tid & 31;
    const int gr = lane >> 2, gc = lane & 3;
    const int wrow = warp * 16;
    const int row0 = blockIdx.x * 128;
    const int kbase = blockIdx.y * 672;
    const int NT = 21;

    const int jj = tid & 15;       // k-pair index (k = 2*jj, 2*jj+1)
    const int rld = tid >> 4;      // row base 0..15

    float acc[4][4];
#pragma unroll
    for (int n = 0; n < 4; n++)
#pragma unroll
        for (int r = 0; r < 4; r++) acc[n][r] = 0.f;

    float2 xv[8];

    // ---- prefetch tile 0 ----
    {
        int kq = kbase + 2 * jj;
        bool ok = (kq < DD);
#pragma unroll
        for (int i = 0; i < 8; i++) {
            int r = row0 + rld + 16 * i;
            xv[i] = ok ? *(const float2*)(x + (size_t)r * DD + kq)
                       : make_float2(0.f, 0.f);
        }
    }

    for (int t = 0; t < NT; t++) {
        __syncthreads();   // previous tile's compute done
#pragma unroll
        for (int i = 0; i < 8; i++) {
            int r = rld + 16 * i;
            *(float2*)&xs[r][2 * jj] = xv[i];
        }
        __syncthreads();

        // ---- prefetch next tile ----
        if (t + 1 < NT) {
            int kq = kbase + (t + 1) * 32 + 2 * jj;
            bool ok = (kq < DD);
#pragma unroll
            for (int i = 0; i < 8; i++) {
                int r = row0 + rld + 16 * i;
                xv[i] = ok ? *(const float2*)(x + (size_t)r * DD + kq)
                           : make_float2(0.f, 0.f);
            }
        }

        const uint4* bf = g_bfrag + (size_t)(blockIdx.y * NT + t) * 256 + lane;

#pragma unroll
        for (int ch = 0; ch < 2; ch++) {
            // B fragments for this chunk (L1-broadcast across warps)
            uint4 B0 = bf[(ch * 4 + 0) * 32];
            uint4 B1 = bf[(ch * 4 + 1) * 32];
            uint4 B2 = bf[(ch * 4 + 2) * 32];
            uint4 B3 = bf[(ch * 4 + 3) * 32];

            // A: 2 wide LDS (rows gr, gr+8), 4 contiguous logical k each
            float4 fa = *(const float4*)&xs[wrow + gr][8 * gc + 4 * ch];
            float4 fb = *(const float4*)&xs[wrow + 8 + gr][8 * gc + 4 * ch];
            unsigned ah0, ah1, ah2, ah3, am0, am1, am2, am3;
            split_pair(fa.x, fa.y, ah0, am0);
            split_pair(fb.x, fb.y, ah1, am1);
            split_pair(fa.z, fa.w, ah2, am2);
            split_pair(fb.z, fb.w, ah3, am3);

            MMA_F16(acc[0], ah0, ah1, ah2, ah3, B0.x, B0.y);
            MMA_F16(acc[0], ah0, ah1, ah2, ah3, B0.z, B0.w);
            MMA_F16(acc[0], am0, am1, am2, am3, B0.x, B0.y);

            MMA_F16(acc[1], ah0, ah1, ah2, ah3, B1.x, B1.y);
            MMA_F16(acc[1], ah0, ah1, ah2, ah3, B1.z, B1.w);
            MMA_F16(acc[1], am0, am1, am2, am3, B1.x, B1.y);

            MMA_F16(acc[2], ah0, ah1, ah2, ah3, B2.x, B2.y);
            MMA_F16(acc[2], ah0, ah1, ah2, ah3, B2.z, B2.w);
            MMA_F16(acc[2], am0, am1, am2, am3, B2.x, B2.y);

            MMA_F16(acc[3], ah0, ah1, ah2, ah3, B3.x, B3.y);
            MMA_F16(acc[3], ah0, ah1, ah2, ah3, B3.z, B3.w);
            MMA_F16(acc[3], am0, am1, am2, am3, B3.x, B3.y);
        }
    }

    // ---- epilogue: write partial ----
    float* gp = blockIdx.y ? g_p1 : g_p0;
    const int rowa = row0 + wrow + gr;
#pragma unroll
    for (int ng = 0; ng < 4; ng++) {
        int col = ng * 8 + 2 * gc;
        *(float2*)&gp[(size_t)rowa * H1C + col] =
            make_float2(acc[ng][0], acc[ng][1]);
        *(float2*)&gp[(size_t)(rowa + 8) * H1C + col] =
            make_float2(acc[ng][2], acc[ng][3]);
    }
}

// ---------------------------------------------------------------------------
// Kernel B: sum partials + bias, conv1d(k=3,pad=1,32->16)+relu, gemm2(16->2).
// ---------------------------------------------------------------------------
__global__ __launch_bounds__(256) void conv_gemm2_kernel(
    const float* __restrict__ conv_w, const float* __restrict__ conv_b,
    const float* __restrict__ w2, const float* __restrict__ b2,
    const float* __restrict__ b1)
{
    __shared__ float hs[258][33];   // halo tile of h1
    __shared__ float wst[96][16];   // [k*32+c1][c2]
    __shared__ float cb[16];
    __shared__ float w2s[16][2];
    __shared__ float b2s[2];
    __shared__ float b1s[32];

    const int tid = threadIdx.x;
    if (blockIdx.x == 0 && tid == 0) g_done = 0;

    for (int i = tid; i < 96 * 16; i += 256) {
        int q = i >> 4, c2 = i & 15;
        int k = q >> 5, c1 = q & 31;
        wst[q][c2] = conv_w[c2 * 96 + c1 * 3 + k];   // conv_w [c2][c1][k]
    }
    if (tid < 16) cb[tid] = conv_b[tid];
    if (tid < 32) { w2s[tid >> 1][tid & 1] = w2[tid]; b1s[tid] = b1[tid]; }
    if (tid < 2) b2s[tid] = b2[tid];
    __syncthreads();

    const int p0 = blockIdx.x * 256;
    const int lblk = p0 & (LL - 1);

    for (int idx = tid; idx < 258 * 32; idx += 256) {
        int row = idx >> 5, c = idx & 31;
        int l = lblk - 1 + row;
        float v = 0.f;
        if (l >= 0 && l < LL) {
            int g = p0 + row - 1;
            v = g_p0[(size_t)g * H1C + c] + g_p1[(size_t)g * H1C + c] + b1s[c];
        }
        hs[row][c] = v;
    }
    __syncthreads();

    float4 acc[4];
#pragma unroll
    for (int m = 0; m < 4; m++) acc[m] = make_float4(0, 0, 0, 0);
#pragma unroll
    for (int kk = 0; kk < 3; kk++) {
#pragma unroll
        for (int c1 = 0; c1 < 32; c1++) {
            float hv = hs[tid + kk][c1];
            int q = kk * 32 + c1;
#pragma unroll
            for (int m = 0; m < 4; m++) {
                float4 w = *(const float4*)&wst[q][m * 4];
                acc[m].x += hv * w.x; acc[m].y += hv * w.y;
                acc[m].z += hv * w.z; acc[m].w += hv * w.w;
            }
        }
    }
    float af[16];
#pragma unroll
    for (int m = 0; m < 4; m++) {
        af[m * 4 + 0] = acc[m].x; af[m * 4 + 1] = acc[m].y;
        af[m * 4 + 2] = acc[m].z; af[m * 4 + 3] = acc[m].w;
    }
    float e0 = b2s[0], e1 = b2s[1];
#pragma unroll
    for (int c2 = 0; c2 < 16; c2++) {
        float h = fmaxf(af[c2] + cb[c2], 0.f);
        e0 += h * w2s[c2][0];
        e1 += h * w2s[c2][1];
    }
    *(float2*)&g_em[(size_t)(p0 + tid) * 2] = make_float2(e0, e1);
}

// ---------------------------------------------------------------------------
// Kernel C: CRF via associative scans (+ merged final reduction).
// ---------------------------------------------------------------------------
__device__ __forceinline__ float lse2(float p, float q) {
    float mx = fmaxf(p, q), mn = fminf(p, q);
    return mx + log1pf(__expf(mn - mx));
}
__device__ __forceinline__ float4 lse_mm(float4 A, float4 B) {
    float4 C;
    C.x = lse2(A.x + B.x, A.y + B.z);
    C.y = lse2(A.x + B.y, A.y + B.w);
    C.z = lse2(A.z + B.x, A.w + B.z);
    C.w = lse2(A.z + B.y, A.w + B.w);
    return C;
}
__device__ __forceinline__ float4 max_mm(float4 A, float4 B) {
    float4 C;
    C.x = fmaxf(A.x + B.x, A.y + B.z);
    C.y = fmaxf(A.x + B.y, A.y + B.w);
    C.z = fmaxf(A.z + B.x, A.w + B.z);
    C.w = fmaxf(A.z + B.y, A.w + B.w);
    return C;
}
__device__ __forceinline__ unsigned comp2(unsigned a, unsigned b) {
    unsigned r0 = (a >> (b & 1)) & 1;
    unsigned r1 = (a >> ((b >> 1) & 1)) & 1;
    return r0 | (r1 << 1);
}

__global__ __launch_bounds__(256) void crf_kernel(
    const int* __restrict__ tlen, const int* __restrict__ labels,
    const float* __restrict__ start_trans, const float* __restrict__ end_trans,
    const float* __restrict__ trans, float* __restrict__ out)
{
    __shared__ float4 sf[256];
    __shared__ float4 sv[256];
    __shared__ unsigned char scomp[256];
    __shared__ float sred[256];

    const int b = blockIdx.x, tid = threadIdx.x;
    const int len = tlen[b];
    const float t00 = trans[0], t01 = trans[1], t10 = trans[2], t11 = trans[3];
    const float* emb = g_em + (size_t)b * LL * 2;

    float4 Pf = make_float4(0.f, NEGINF, NEGINF, 0.f);
    float4 Pv = Pf;
#pragma unroll
    for (int k = 1; k <= 8; k++) {
        int t = tid * 8 + k;
        if (t < len) {
            float m0 = emb[2 * t], m1 = emb[2 * t + 1];
            float4 M = make_float4(t00 + m0, t01 + m1, t10 + m0, t11 + m1);
            Pf = lse_mm(Pf, M);
            Pv = max_mm(Pv, M);
        }
    }
    sf[tid] = Pf; sv[tid] = Pv;
    __syncthreads();

    for (int off = 1; off < 256; off <<= 1) {
        float4 nf, nv;
        bool p = (tid >= off);
        if (p) { nf = lse_mm(sf[tid - off], sf[tid]); nv = max_mm(sv[tid - off], sv[tid]); }
        __syncthreads();
        if (p) { sf[tid] = nf; sv[tid] = nv; }
        __syncthreads();
    }

    const float a00 = start_trans[0] + emb[0];
    const float a01 = start_trans[1] + emb[1];
    const float e0 = end_trans[0], e1 = end_trans[1];

    float4 PF = sf[255];
    float f0 = lse2(a00 + PF.x, a01 + PF.z);
    float f1 = lse2(a00 + PF.y, a01 + PF.w);
    float norm = lse2(f0 + e0, f1 + e1);

    float4 PV = sv[255];
    float v0 = fmaxf(a00 + PV.x, a01 + PV.z);
    float v1 = fmaxf(a00 + PV.y, a01 + PV.w);
    int last = (v1 + e1 > v0 + e0) ? 1 : 0;

    float4 E = (tid == 0) ? make_float4(0.f, NEGINF, NEGINF, 0.f) : sv[tid - 1];
    float u0 = fmaxf(a00 + E.x, a01 + E.z);
    float u1 = fmaxf(a00 + E.y, a01 + E.w);
    unsigned g[8];
    unsigned cc = 2u;   // identity map
#pragma unroll
    for (int k = 1; k <= 8; k++) {
        int t = tid * 8 + k;
        unsigned gt;
        if (t < len) {
            float m0 = emb[2 * t], m1 = emb[2 * t + 1];
            float s00 = u0 + t00, s10 = u1 + t10;
            int i0 = (s10 > s00) ? 1 : 0;
            float n0 = fmaxf(s00, s10) + m0;
            float s01 = u0 + t01, s11 = u1 + t11;
            int i1 = (s11 > s01) ? 1 : 0;
            float n1 = fmaxf(s01, s11) + m1;
            gt = (unsigned)(i0 | (i1 << 1));
            u0 = n0; u1 = n1;
        } else {
            gt = 2u;   // identity
        }
        g[k - 1] = gt;
        cc = comp2(cc, gt);
    }
    scomp[tid] = (unsigned char)cc;
    __syncthreads();

    for (int off = 1; off < 256; off <<= 1) {
        unsigned nc = 0;
        bool p = (tid + off < 256);
        if (p) nc = comp2(scomp[tid], scomp[tid + off]);
        __syncthreads();
        if (p) scomp[tid] = (unsigned char)nc;
        __syncthreads();
    }
    unsigned suf_next = (tid == 255) ? 2u : (unsigned)scomp[tid + 1];
    unsigned xx = (suf_next >> last) & 1u;

    float* tout = out + 1 + (size_t)b * LL;
#pragma unroll
    for (int k = 8; k >= 1; k--) {
        xx = (g[k - 1] >> xx) & 1u;
        int pos = tid * 8 + k - 1;
        tout[pos] = (pos < len) ? (float)xx : 0.f;
    }

    const int* lab = labels + (size_t)b * LL;
    float sc = 0.f;
#pragma unroll
    for (int k = 1; k <= 8; k++) {
        int t = tid * 8 + k;
        if (t < len) {
            int lp = lab[t - 1], lc = lab[t];
            sc += trans[lp * 2 + lc] + emb[2 * t + lc];
        }
    }
    sred[tid] = sc;
    __syncthreads();
    for (int off = 128; off > 0; off >>= 1) {
        if (tid < off) sred[tid] += sred[tid + off];
        __syncthreads();
    }
    if (tid == 0) {
        int l0 = lab[0];
        float total = sred[0] + start_trans[l0] + emb[l0];
        int le = lab[len - 1];
        total += end_trans[le];
        g_llh[b] = total - norm;
        __threadfence();
        unsigned old = atomicAdd(&g_done, 1);
        if (old == BB - 1) {
            __threadfence();
            float s = 0.f;
#pragma unroll
            for (int i = 0; i < BB; i++) s += ((volatile float*)g_llh)[i];
            out[0] = -s;
        }
    }
}

extern "C" void kernel_launch(void* const* d_in, const int* in_sizes, int n_in,
                              void* d_out, int out_size)
{
    const float* x       = (const float*)d_in[0];
    const int*   tlen    = (const int*)d_in[1];
    const int*   labels  = (const int*)d_in[2];
    const float* w1      = (const float*)d_in[3];
    const float* b1      = (const float*)d_in[4];
    const float* conv_w  = (const float*)d_in[5];
    const float* conv_b  = (const float*)d_in[6];
    const float* w2      = (const float*)d_in[7];
    const float* b2      = (const float*)d_in[8];
    const float* st      = (const float*)d_in[9];
    const float* en      = (const float*)d_in[10];
    const float* tr      = (const float*)d_in[11];
    float* out = (float*)d_out;

    prep_b<<<42, 256>>>(w1);
    gemm1_mma<<<dim3(128, 2), 256>>>(x);
    conv_gemm2_kernel<<<64, 256>>>(conv_w, conv_b, w2, b2, b1);
    crf_kernel<<<BB, 256>>>(tlen, labels, st, en, tr, out);
}

// round 5
// speedup vs baseline: 1.5920x; 1.2600x over previous
#include <cuda_runtime.h>
#include <cuda_bf16.h>
#include <cuda_fp16.h>
#include <math.h>

// Problem constants
#define BB 8
#define LL 2048
#define DD 1330
#define H1C 32
// T = 2 (hardcoded throughout)

#define NEGINF (-1e30f)
#define NTILE 42          // 2 slices * 21 tiles of 32 k

// Scratch (device globals; no allocation allowed)
__device__ float g_p0[BB * LL * H1C];   // split-K partial 0
__device__ float g_p1[BB * LL * H1C];   // split-K partial 1
__device__ float g_em[BB * LL * 2];     // [B*L, 2]
__device__ float g_llh[BB];
__device__ unsigned g_done;
// B fragments, fragment-order: [tile][ch][ng][lane] -> {bh0,bh1,bm0,bm1}
__device__ uint4 g_bfrag[NTILE * 2 * 4 * 32];

// ---------------------------------------------------------------------------
// fp16 helpers
// ---------------------------------------------------------------------------
__device__ __forceinline__ void split_pair(float f0, float f1,
                                           unsigned& hi, unsigned& mid) {
    __half h0 = __float2half_rn(f0), h1 = __float2half_rn(f1);
    float r0 = f0 - __half2float(h0);
    float r1 = f1 - __half2float(h1);
    __half2 H = __halves2half2(h0, h1);
    __half2 M = __halves2half2(__float2half_rn(r0), __float2half_rn(r1));
    hi = *(unsigned*)&H;
    mid = *(unsigned*)&M;
}

#define MMA_F16(c, a0, a1, a2, a3, b0, b1)                                    \
    asm volatile(                                                             \
        "mma.sync.aligned.m16n8k16.row.col.f32.f16.f16.f32 "                  \
        "{%0,%1,%2,%3}, {%4,%5,%6,%7}, {%8,%9}, {%0,%1,%2,%3};"               \
        : "+f"(c[0]), "+f"(c[1]), "+f"(c[2]), "+f"(c[3])                      \
        : "r"(a0), "r"(a1), "r"(a2), "r"(a3), "r"(b0), "r"(b1))

// ---------------------------------------------------------------------------
// Kernel 0: precompute B fragments (hi/mid fp16 split of w1, fragment order).
// Logical k mapping within a 32-k tile: k = 8*gc + 4*ch + {0,1,2,3}
// ---------------------------------------------------------------------------
__global__ __launch_bounds__(256) void prep_b(const float* __restrict__ w1) {
    int idx = blockIdx.x * 256 + threadIdx.x;   // 0 .. 10751
    int lane = idx & 31;
    int ng = (idx >> 5) & 3;
    int ch = (idx >> 7) & 1;
    int t = idx >> 8;
    if (t >= NTILE) return;
    int gr = lane >> 2, gc = lane & 3;
    int c = ng * 8 + gr;
    int kb = t * 32 + 8 * gc + 4 * ch;
    float f[4];
#pragma unroll
    for (int b = 0; b < 4; b++) {
        int k = kb + b;
        f[b] = (k < DD) ? w1[k * H1C + c] : 0.f;
    }
    uint4 o;
    split_pair(f[0], f[1], o.x, o.z);   // b0 hi, b0 mid
    split_pair(f[2], f[3], o.y, o.w);   // b1 hi, b1 mid
    g_bfrag[idx] = o;
}

// ---------------------------------------------------------------------------
// Kernel A: partial = x @ w1 over a K-slice, 3xFP16-split tensor GEMM.
// Direct-from-global A fragments (no smem, no syncthreads).
// Block: 256 threads (8 warps), BM=128; warp w: rows 16w..16w+15, cols 0..31.
// ---------------------------------------------------------------------------
__device__ __forceinline__ float2 ld2g(const float* __restrict__ r, int k) {
    // k is even; DD even => k+1 < DD  <=>  k < DD
    return (k < DD) ? *(const float2*)(r + k) : make_float2(0.f, 0.f);
}

__global__ __launch_bounds__(256, 2) void gemm1_mma(const float* __restrict__ x)
{
    const int tid = threadIdx.x;
    const int warp = tid >> 5, lane = tid & 31;
    const int gr = lane >> 2, gc = lane & 3;
    const int row0 = blockIdx.x * 128;
    const int kbase = blockIdx.y * 672;

    const float* __restrict__ rowA = x + (size_t)(row0 + warp * 16 + gr) * DD;
    const float* __restrict__ rowB = rowA + 8 * (size_t)DD;

    float acc[4][4];
#pragma unroll
    for (int n = 0; n < 4; n++)
#pragma unroll
        for (int r = 0; r < 4; r++) acc[n][r] = 0.f;

    // cur[ch*4+0] = (row gr,  k0..k1), +1 = (row gr,  k2..k3)
    // cur[ch*4+2] = (row gr+8,k0..k1), +3 = (row gr+8,k2..k3)
    float2 cur[8], nxt[8];
    {
        int kq0 = kbase + 8 * gc;
#pragma unroll
        for (int ch = 0; ch < 2; ch++) {
            int kq = kq0 + 4 * ch;
            cur[ch * 4 + 0] = ld2g(rowA, kq);
            cur[ch * 4 + 1] = ld2g(rowA, kq + 2);
            cur[ch * 4 + 2] = ld2g(rowB, kq);
            cur[ch * 4 + 3] = ld2g(rowB, kq + 2);
        }
    }

#pragma unroll
    for (int t = 0; t < 21; t++) {
        // prefetch next tile
        if (t < 20) {
            int kq0 = kbase + (t + 1) * 32 + 8 * gc;
#pragma unroll
            for (int ch = 0; ch < 2; ch++) {
                int kq = kq0 + 4 * ch;
                nxt[ch * 4 + 0] = ld2g(rowA, kq);
                nxt[ch * 4 + 1] = ld2g(rowA, kq + 2);
                nxt[ch * 4 + 2] = ld2g(rowB, kq);
                nxt[ch * 4 + 3] = ld2g(rowB, kq + 2);
            }
        }

        const uint4* __restrict__ bf =
            g_bfrag + (size_t)(blockIdx.y * 21 + t) * 256 + lane;

#pragma unroll
        for (int ch = 0; ch < 2; ch++) {
            uint4 B0 = bf[ch * 128 + 0];
            uint4 B1 = bf[ch * 128 + 32];
            uint4 B2 = bf[ch * 128 + 64];
            uint4 B3 = bf[ch * 128 + 96];

            float2 p0 = cur[ch * 4 + 0], p1 = cur[ch * 4 + 1];
            float2 q0 = cur[ch * 4 + 2], q1 = cur[ch * 4 + 3];
            unsigned ah0, ah1, ah2, ah3, am0, am1, am2, am3;
            split_pair(p0.x, p0.y, ah0, am0);
            split_pair(q0.x, q0.y, ah1, am1);
            split_pair(p1.x, p1.y, ah2, am2);
            split_pair(q1.x, q1.y, ah3, am3);

            MMA_F16(acc[0], ah0, ah1, ah2, ah3, B0.x, B0.y);
            MMA_F16(acc[0], ah0, ah1, ah2, ah3, B0.z, B0.w);
            MMA_F16(acc[0], am0, am1, am2, am3, B0.x, B0.y);

            MMA_F16(acc[1], ah0, ah1, ah2, ah3, B1.x, B1.y);
            MMA_F16(acc[1], ah0, ah1, ah2, ah3, B1.z, B1.w);
            MMA_F16(acc[1], am0, am1, am2, am3, B1.x, B1.y);

            MMA_F16(acc[2], ah0, ah1, ah2, ah3, B2.x, B2.y);
            MMA_F16(acc[2], ah0, ah1, ah2, ah3, B2.z, B2.w);
            MMA_F16(acc[2], am0, am1, am2, am3, B2.x, B2.y);

            MMA_F16(acc[3], ah0, ah1, ah2, ah3, B3.x, B3.y);
            MMA_F16(acc[3], ah0, ah1, ah2, ah3, B3.z, B3.w);
            MMA_F16(acc[3], am0, am1, am2, am3, B3.x, B3.y);
        }

#pragma unroll
        for (int i = 0; i < 8; i++) cur[i] = nxt[i];
    }

    // ---- epilogue: write partial ----
    float* gp = blockIdx.y ? g_p1 : g_p0;
    const int rowa = row0 + warp * 16 + gr;
#pragma unroll
    for (int ng = 0; ng < 4; ng++) {
        int col = ng * 8 + 2 * gc;
        *(float2*)&gp[(size_t)rowa * H1C + col] =
            make_float2(acc[ng][0], acc[ng][1]);
        *(float2*)&gp[(size_t)(rowa + 8) * H1C + col] =
            make_float2(acc[ng][2], acc[ng][3]);
    }
}

// ---------------------------------------------------------------------------
// Kernel B: sum partials + bias, conv1d(k=3,pad=1,32->16)+relu, gemm2(16->2).
// 128 blocks x 128 threads; block covers 128 positions.
// ---------------------------------------------------------------------------
__global__ __launch_bounds__(128) void conv_gemm2_kernel(
    const float* __restrict__ conv_w, const float* __restrict__ conv_b,
    const float* __restrict__ w2, const float* __restrict__ b2,
    const float* __restrict__ b1)
{
    __shared__ float hs[130][33];   // halo tile of h1
    __shared__ float wst[96][16];   // [k*32+c1][c2]
    __shared__ float cb[16];
    __shared__ float w2s[16][2];
    __shared__ float b2s[2];
    __shared__ float b1s[32];

    const int tid = threadIdx.x;
    if (blockIdx.x == 0 && tid == 0) g_done = 0;

    for (int i = tid; i < 96 * 16; i += 128) {
        int q = i >> 4, c2 = i & 15;
        int k = q >> 5, c1 = q & 31;
        wst[q][c2] = conv_w[c2 * 96 + c1 * 3 + k];   // conv_w [c2][c1][k]
    }
    if (tid < 16) cb[tid] = conv_b[tid];
    if (tid < 32) { w2s[tid >> 1][tid & 1] = w2[tid]; b1s[tid] = b1[tid]; }
    if (tid < 2) b2s[tid] = b2[tid];
    __syncthreads();

    const int p0 = blockIdx.x * 128;
    const int lblk = p0 & (LL - 1);

    for (int idx = tid; idx < 130 * 32; idx += 128) {
        int row = idx >> 5, c = idx & 31;
        int l = lblk - 1 + row;
        float v = 0.f;
        if (l >= 0 && l < LL) {
            int g = p0 + row - 1;
            v = g_p0[(size_t)g * H1C + c] + g_p1[(size_t)g * H1C + c] + b1s[c];
        }
        hs[row][c] = v;
    }
    __syncthreads();

    float4 acc[4];
#pragma unroll
    for (int m = 0; m < 4; m++) acc[m] = make_float4(0, 0, 0, 0);
#pragma unroll
    for (int kk = 0; kk < 3; kk++) {
#pragma unroll
        for (int c1 = 0; c1 < 32; c1++) {
            float hv = hs[tid + kk][c1];
            int q = kk * 32 + c1;
#pragma unroll
            for (int m = 0; m < 4; m++) {
                float4 w = *(const float4*)&wst[q][m * 4];
                acc[m].x += hv * w.x; acc[m].y += hv * w.y;
                acc[m].z += hv * w.z; acc[m].w += hv * w.w;
            }
        }
    }
    float af[16];
#pragma unroll
    for (int m = 0; m < 4; m++) {
        af[m * 4 + 0] = acc[m].x; af[m * 4 + 1] = acc[m].y;
        af[m * 4 + 2] = acc[m].z; af[m * 4 + 3] = acc[m].w;
    }
    float e0 = b2s[0], e1 = b2s[1];
#pragma unroll
    for (int c2 = 0; c2 < 16; c2++) {
        float h = fmaxf(af[c2] + cb[c2], 0.f);
        e0 += h * w2s[c2][0];
        e1 += h * w2s[c2][1];
    }
    *(float2*)&g_em[(size_t)(p0 + tid) * 2] = make_float2(e0, e1);
}

// ---------------------------------------------------------------------------
// Kernel C: CRF via associative scans (+ merged final reduction).
// ---------------------------------------------------------------------------
__device__ __forceinline__ float lse2(float p, float q) {
    float mx = fmaxf(p, q), mn = fminf(p, q);
    return mx + __logf(1.f + __expf(mn - mx));
}
__device__ __forceinline__ float4 lse_mm(float4 A, float4 B) {
    float4 C;
    C.x = lse2(A.x + B.x, A.y + B.z);
    C.y = lse2(A.x + B.y, A.y + B.w);
    C.z = lse2(A.z + B.x, A.w + B.z);
    C.w = lse2(A.z + B.y, A.w + B.w);
    return C;
}
__device__ __forceinline__ float4 max_mm(float4 A, float4 B) {
    float4 C;
    C.x = fmaxf(A.x + B.x, A.y + B.z);
    C.y = fmaxf(A.x + B.y, A.y + B.w);
    C.z = fmaxf(A.z + B.x, A.w + B.z);
    C.w = fmaxf(A.z + B.y, A.w + B.w);
    return C;
}
__device__ __forceinline__ unsigned comp2(unsigned a, unsigned b) {
    unsigned r0 = (a >> (b & 1)) & 1;
    unsigned r1 = (a >> ((b >> 1) & 1)) & 1;
    return r0 | (r1 << 1);
}

__global__ __launch_bounds__(256) void crf_kernel(
    const int* __restrict__ tlen, const int* __restrict__ labels,
    const float* __restrict__ start_trans, const float* __restrict__ end_trans,
    const float* __restrict__ trans, float* __restrict__ out)
{
    __shared__ float4 sf[256];
    __shared__ float4 sv[256];
    __shared__ unsigned char scomp[256];
    __shared__ float sred[256];

    const int b = blockIdx.x, tid = threadIdx.x;
    const int len = tlen[b];
    const float t00 = trans[0], t01 = trans[1], t10 = trans[2], t11 = trans[3];
    const float* emb = g_em + (size_t)b * LL * 2;

    // cache this thread's 8 emission pairs (steps tid*8+1 .. tid*8+8)
    float2 em[8];
#pragma unroll
    for (int k = 1; k <= 8; k++) {
        int t = tid * 8 + k;
        em[k - 1] = (t < LL) ? *(const float2*)(emb + 2 * t)
                             : make_float2(0.f, 0.f);
    }

    float4 Pf = make_float4(0.f, NEGINF, NEGINF, 0.f);
    float4 Pv = Pf;
#pragma unroll
    for (int k = 1; k <= 8; k++) {
        int t = tid * 8 + k;
        if (t < len) {
            float m0 = em[k - 1].x, m1 = em[k - 1].y;
            float4 M = make_float4(t00 + m0, t01 + m1, t10 + m0, t11 + m1);
            Pf = lse_mm(Pf, M);
            Pv = max_mm(Pv, M);
        }
    }
    sf[tid] = Pf; sv[tid] = Pv;
    __syncthreads();

    for (int off = 1; off < 256; off <<= 1) {
        float4 nf, nv;
        bool p = (tid >= off);
        if (p) { nf = lse_mm(sf[tid - off], sf[tid]); nv = max_mm(sv[tid - off], sv[tid]); }
        __syncthreads();
        if (p) { sf[tid] = nf; sv[tid] = nv; }
        __syncthreads();
    }

    const float a00 = start_trans[0] + emb[0];
    const float a01 = start_trans[1] + emb[1];
    const float e0 = end_trans[0], e1 = end_trans[1];

    float4 PF = sf[255];
    float f0 = lse2(a00 + PF.x, a01 + PF.z);
    float f1 = lse2(a00 + PF.y, a01 + PF.w);
    float norm = lse2(f0 + e0, f1 + e1);

    float4 PV = sv[255];
    float v0 = fmaxf(a00 + PV.x, a01 + PV.z);
    float v1 = fmaxf(a00 + PV.y, a01 + PV.w);
    int last = (v1 + e1 > v0 + e0) ? 1 : 0;

    float4 E = (tid == 0) ? make_float4(0.f, NEGINF, NEGINF, 0.f) : sv[tid - 1];
    float u0 = fmaxf(a00 + E.x, a01 + E.z);
    float u1 = fmaxf(a00 + E.y, a01 + E.w);
    unsigned g[8];
    unsigned cc = 2u;   // identity map
#pragma unroll
    for (int k = 1; k <= 8; k++) {
        int t = tid * 8 + k;
        unsigned gt;
        if (t < len) {
            float m0 = em[k - 1].x, m1 = em[k - 1].y;
            float s00 = u0 + t00, s10 = u1 + t10;
            int i0 = (s10 > s00) ? 1 : 0;
            float n0 = fmaxf(s00, s10) + m0;
            float s01 = u0 + t01, s11 = u1 + t11;
            int i1 = (s11 > s01) ? 1 : 0;
            float n1 = fmaxf(s01, s11) + m1;
            gt = (unsigned)(i0 | (i1 << 1));
            u0 = n0; u1 = n1;
        } else {
            gt = 2u;   // identity
        }
        g[k - 1] = gt;
        cc = comp2(cc, gt);
    }
    scomp[tid] = (unsigned char)cc;
    __syncthreads();

    for (int off = 1; off < 256; off <<= 1) {
        unsigned nc = 0;
        bool p = (tid + off < 256);
        if (p) nc = comp2(scomp[tid], scomp[tid + off]);
        __syncthreads();
        if (p) scomp[tid] = (unsigned char)nc;
        __syncthreads();
    }
    unsigned suf_next = (tid == 255) ? 2u : (unsigned)scomp[tid + 1];
    unsigned xx = (suf_next >> last) & 1u;

    float* tout = out + 1 + (size_t)b * LL;
#pragma unroll
    for (int k = 8; k >= 1; k--) {
        xx = (g[k - 1] >> xx) & 1u;
        int pos = tid * 8 + k - 1;
        tout[pos] = (pos < len) ? (float)xx : 0.f;
    }

    const int* lab = labels + (size_t)b * LL;
    float sc = 0.f;
#pragma unroll
    for (int k = 1; k <= 8; k++) {
        int t = tid * 8 + k;
        if (t < len) {
            int lp = lab[t - 1], lc = lab[t];
            sc += trans[lp * 2 + lc] + (lc ? em[k - 1].y : em[k - 1].x);
        }
    }
    sred[tid] = sc;
    __syncthreads();
    for (int off = 128; off > 0; off >>= 1) {
        if (tid < off) sred[tid] += sred[tid + off];
        __syncthreads();
    }
    if (tid == 0) {
        int l0 = lab[0];
        float total = sred[0] + start_trans[l0] + emb[l0];
        int le = lab[len - 1];
        total += end_trans[le];
        g_llh[b] = total - norm;
        __threadfence();
        unsigned old = atomicAdd(&g_done, 1);
        if (old == BB - 1) {
            __threadfence();
            float s = 0.f;
#pragma unroll
            for (int i = 0; i < BB; i++) s += ((volatile float*)g_llh)[i];
            out[0] = -s;
        }
    }
}

extern "C" void kernel_launch(void* const* d_in, const int* in_sizes, int n_in,
                              void* d_out, int out_size)
{
    const float* x       = (const float*)d_in[0];
    const int*   tlen    = (const int*)d_in[1];
    const int*   labels  = (const int*)d_in[2];
    const float* w1      = (const float*)d_in[3];
    const float* b1      = (const float*)d_in[4];
    const float* conv_w  = (const float*)d_in[5];
    const float* conv_b  = (const float*)d_in[6];
    const float* w2      = (const float*)d_in[7];
    const float* b2      = (const float*)d_in[8];
    const float* st      = (const float*)d_in[9];
    const float* en      = (const float*)d_in[10];
    const float* tr      = (const float*)d_in[11];
    float* out = (float*)d_out;

    prep_b<<<42, 256>>>(w1);
    gemm1_mma<<<dim3(128, 2), 256>>>(x);
    conv_gemm2_kernel<<<128, 128>>>(conv_w, conv_b, w2, b2, b1);
    crf_kernel<<<BB, 256>>>(tlen, labels, st, en, tr, out);
}